// round 4
// baseline (speedup 1.0000x reference)
#include <cuda_runtime.h>
#include <cstdint>

// GCNStage4_ReduceSum: out[t] += msg[e] for t = edge_index[1][e]
// msg: [NUM_EDGES, 32] f32; edge_index: [2, NUM_EDGES] int32 (harness); out: [num_nodes, 32] f32
//
// R4: half-row per thread. Thread h -> edge e=h>>1, half=h&1.
//   1 tgt load + 4 consecutive float4 loads (front-batched, MLP=5) + 4 RED.v4.f32
//   to consecutive addresses. Low register count -> full occupancy AND high MLP.

#define FEAT 32

__global__ void __launch_bounds__(256) scatter_add_kernel(
        const float4* __restrict__ msg4,
        const int* __restrict__ tgt,
        float* __restrict__ out,
        int num_half)    // num_edges * 2
{
    int h = blockIdx.x * blockDim.x + threadIdx.x;
    if (h >= num_half) return;

    int e    = h >> 1;
    int half = h & 1;

    int t = tgt[e];                                    // 16 consecutive int32s per warp
    const float4* src = msg4 + (size_t)e * 8 + half * 4;

    // front-batched loads: 4 LDG.128 + the tgt LDG in flight together
    float4 v0 = __ldcs(src + 0);
    float4 v1 = __ldcs(src + 1);
    float4 v2 = __ldcs(src + 2);
    float4 v3 = __ldcs(src + 3);

    float* dst = out + (size_t)t * FEAT + half * 16;
    asm volatile("red.global.add.v4.f32 [%0], {%1, %2, %3, %4};"
                 :: "l"(dst +  0), "f"(v0.x), "f"(v0.y), "f"(v0.z), "f"(v0.w) : "memory");
    asm volatile("red.global.add.v4.f32 [%0], {%1, %2, %3, %4};"
                 :: "l"(dst +  4), "f"(v1.x), "f"(v1.y), "f"(v1.z), "f"(v1.w) : "memory");
    asm volatile("red.global.add.v4.f32 [%0], {%1, %2, %3, %4};"
                 :: "l"(dst +  8), "f"(v2.x), "f"(v2.y), "f"(v2.z), "f"(v2.w) : "memory");
    asm volatile("red.global.add.v4.f32 [%0], {%1, %2, %3, %4};"
                 :: "l"(dst + 12), "f"(v3.x), "f"(v3.y), "f"(v3.z), "f"(v3.w) : "memory");
}

extern "C" void kernel_launch(void* const* d_in, const int* in_sizes, int n_in,
                              void* d_out, int out_size) {
    const float4* msg4 = (const float4*)d_in[0];
    const int*    ei   = (const int*)d_in[1];   // int32 indices
    float*        out  = (float*)d_out;

    int num_edges = in_sizes[0] / FEAT;          // 1,600,000
    const int* tgt = ei + num_edges;             // row 1 of edge_index

    // 1) zero the output (poisoned to 0xAA by harness); memset is capturable
    cudaMemsetAsync(d_out, 0, (size_t)out_size * sizeof(float));

    // 2) scatter-add: one thread per half-row (16 floats)
    int num_half = num_edges * 2;                // 3.2M
    int threads = 256;
    int blocks = (num_half + threads - 1) / threads;   // 12500 exact
    scatter_add_kernel<<<blocks, threads>>>(msg4, tgt, out, num_half);
}

// round 5
// speedup vs baseline: 1.5222x; 1.5222x over previous
#include <cuda_runtime.h>
#include <cstdint>

// GCNStage4_ReduceSum: out[t] += msg[e] for t = edge_index[1][e]
// msg: [NUM_EDGES, 32] f32; edge_index: [2, NUM_EDGES] int32 (harness); out: [num_nodes, 32] f32
//
// R5: R3's contiguous lane mapping (lanes 0..7 = one edge row, perfectly
// coalesced LDG.128) + register-lean x4 unroll:
//   fragment id = blockIdx.x*1024 + tid + 256*u  ->  sub invariant, e_u = e0 + 32u.
// Front-batched loads (MLP=8), fire-and-forget red.global.add.v4.f32.

#define FEAT 32

__global__ void __launch_bounds__(256) scatter_add_main(
        const float4* __restrict__ msg4,
        const int* __restrict__ tgt,
        float* __restrict__ out)
{
    int tid  = threadIdx.x;
    int base = blockIdx.x * 1024 + tid;       // fragment id for u=0
    int e0   = base >> 3;
    int sub  = tid & 7;                       // invariant across u

    const float4* src = msg4 + (size_t)e0 * 8 + sub;

    // front-batched loads: 4 tgt + 4 msg in flight together
    int t0 = tgt[e0];
    int t1 = tgt[e0 + 32];
    int t2 = tgt[e0 + 64];
    int t3 = tgt[e0 + 96];
    float4 v0 = __ldcs(src);
    float4 v1 = __ldcs(src + 256);
    float4 v2 = __ldcs(src + 512);
    float4 v3 = __ldcs(src + 768);

    int off = sub * 4;
    asm volatile("red.global.add.v4.f32 [%0], {%1, %2, %3, %4};"
                 :: "l"(out + (size_t)t0 * FEAT + off), "f"(v0.x), "f"(v0.y), "f"(v0.z), "f"(v0.w) : "memory");
    asm volatile("red.global.add.v4.f32 [%0], {%1, %2, %3, %4};"
                 :: "l"(out + (size_t)t1 * FEAT + off), "f"(v1.x), "f"(v1.y), "f"(v1.z), "f"(v1.w) : "memory");
    asm volatile("red.global.add.v4.f32 [%0], {%1, %2, %3, %4};"
                 :: "l"(out + (size_t)t2 * FEAT + off), "f"(v2.x), "f"(v2.y), "f"(v2.z), "f"(v2.w) : "memory");
    asm volatile("red.global.add.v4.f32 [%0], {%1, %2, %3, %4};"
                 :: "l"(out + (size_t)t3 * FEAT + off), "f"(v3.x), "f"(v3.y), "f"(v3.z), "f"(v3.w) : "memory");
}

// Tail: one thread per remaining fragment (simple, guarded).
__global__ void __launch_bounds__(256) scatter_add_tail(
        const float4* __restrict__ msg4,
        const int* __restrict__ tgt,
        float* __restrict__ out,
        int frag_start, int num_frags)
{
    int id = frag_start + blockIdx.x * blockDim.x + threadIdx.x;
    if (id >= num_frags) return;
    int e = id >> 3, sub = id & 7;
    int t = tgt[e];
    float4 v = __ldcs(&msg4[(size_t)e * 8 + sub]);
    float* dst = out + (size_t)t * FEAT + sub * 4;
    asm volatile("red.global.add.v4.f32 [%0], {%1, %2, %3, %4};"
                 :: "l"(dst), "f"(v.x), "f"(v.y), "f"(v.z), "f"(v.w) : "memory");
}

extern "C" void kernel_launch(void* const* d_in, const int* in_sizes, int n_in,
                              void* d_out, int out_size) {
    const float4* msg4 = (const float4*)d_in[0];
    const int*    ei   = (const int*)d_in[1];   // int32 indices
    float*        out  = (float*)d_out;

    int num_edges = in_sizes[0] / FEAT;          // 1,600,000
    const int* tgt = ei + num_edges;             // row 1 of edge_index

    // 1) zero the output (poisoned to 0xAA by harness); memset is capturable
    cudaMemsetAsync(d_out, 0, (size_t)out_size * sizeof(float));

    // 2) scatter-add: main guard-free kernel covers 1024 fragments per block
    int num_frags  = num_edges * 8;              // 12.8M
    int full_blocks = num_frags / 1024;          // 12500 (exact here)
    int rem_start   = full_blocks * 1024;
    if (full_blocks > 0)
        scatter_add_main<<<full_blocks, 256>>>(msg4, tgt, out);
    int rem = num_frags - rem_start;
    if (rem > 0)
        scatter_add_tail<<<(rem + 255) / 256, 256>>>(msg4, tgt, out, rem_start, num_frags);
}